// round 5
// baseline (speedup 1.0000x reference)
#include <cuda_runtime.h>

// float32(3.4 * 3.4), exactly jnp.float32(RADIUS * RADIUS)
#define RADIUS2 11.559999465942383f
#define NSAMPLE 5
#define NBATCH  8

// sq = (x0*x0 + x1*x1) + x2*x2, each op rounded once (XLA CPU 3-elt reduce).
__device__ __forceinline__ float sq3(float x0, float x1, float x2) {
    return __fadd_rn(__fadd_rn(__fmul_rn(x0, x0), __fmul_rn(x1, x1)),
                     __fmul_rn(x2, x2));
}

// pointnet2 ball_query matching the reference's expanded distance:
//   d2 = (sq_q + sq_k) - 2*dot(x_q, x_k)
// dot accumulated ascending with FMA from 0 (Eigen-style): fma(z.., fma(y.., x*x)).
__global__ void ball_query_kernel(const float* __restrict__ x,    // [B, N, 3]
                                  float* __restrict__ out,        // [B, N, NSAMPLE] float32
                                  int n_rows, int n_per_batch)
{
    int stride = gridDim.x * blockDim.x;
    for (int row = blockIdx.x * blockDim.x + threadIdx.x; row < n_rows; row += stride) {
        int b = row / n_per_batch;
        int q = row - b * n_per_batch;
        const float* xb = x + (long long)b * n_per_batch * 3;

        float qx = xb[q * 3 + 0];
        float qy = xb[q * 3 + 1];
        float qz = xb[q * 3 + 2];
        float sqq = sq3(qx, qy, qz);

        int i0 = 0, i1 = 0, i2 = 0, i3 = 0, i4 = 0;
        int cnt = 0;

        for (int k = 0; k < n_per_batch; k++) {
            float bx = xb[k * 3 + 0];
            float by = xb[k * 3 + 1];
            float bz = xb[k * 3 + 2];
            float sqk = sq3(bx, by, bz);
            float dot = __fmaf_rn(qz, bz, __fmaf_rn(qy, by, __fmul_rn(qx, bx)));
            float d2  = __fsub_rn(__fadd_rn(sqq, sqk), __fmul_rn(2.0f, dot));

            if (d2 < RADIUS2) {
                if (cnt == 0) {
                    i0 = k; i1 = k; i2 = k; i3 = k; i4 = k;
                } else if (cnt == 1) {
                    i1 = k;
                } else if (cnt == 2) {
                    i2 = k;
                } else if (cnt == 3) {
                    i3 = k;
                } else {
                    i4 = k;
                }
                cnt++;
                if (cnt == NSAMPLE) break;
            }
        }

        // Output dtype is float32 (indices are < 2^24, exactly representable).
        float* o = out + (long long)row * NSAMPLE;
        o[0] = (float)i0;
        o[1] = (float)i1;
        o[2] = (float)i2;
        o[3] = (float)i3;
        o[4] = (float)i4;
    }
}

extern "C" void kernel_launch(void* const* d_in, const int* in_sizes, int n_in,
                              void* d_out, int out_size) {
    const float* x = (const float*)d_in[0];
    float* out = (float*)d_out;

    int n_rows = out_size / NSAMPLE;       // B * N query rows
    int total_pts = in_sizes[0] / 3;       // B * N points
    int n_per_batch = total_pts / NBATCH;  // N

    int threads = 256;
    int blocks = (n_rows + threads - 1) / threads;
    ball_query_kernel<<<blocks, threads>>>(x, out, n_rows, n_per_batch);
}

// round 6
// speedup vs baseline: 1.2068x; 1.2068x over previous
#include <cuda_runtime.h>

// float32(3.4 * 3.4), exactly jnp.float32(RADIUS * RADIUS)
#define RADIUS2 11.559999465942383f
#define NSAMPLE 5
#define NBATCH  8

// sq = (x0*x0 + x1*x1) + x2*x2, each op rounded once — identical bits to the
// version that passed with rel_err 0.0.
__device__ __forceinline__ float sq3(float x0, float x1, float x2) {
    return __fadd_rn(__fadd_rn(__fmul_rn(x0, x0), __fmul_rn(x1, x1)),
                     __fmul_rn(x2, x2));
}

// One warp per query row. Each warp-iteration tests 32 candidates; ballot +
// ffs extracts hits in ascending-k order (== reference scan order), with
// first-hit backfill. Early-exits once NSAMPLE hits are collected.
__global__ void ball_query_warp_kernel(const float* __restrict__ x,  // [B, N, 3]
                                       float* __restrict__ out,      // [B, N, NSAMPLE]
                                       int n_rows, int n_per_batch)
{
    int gtid = blockIdx.x * blockDim.x + threadIdx.x;
    int row  = gtid >> 5;
    int lane = gtid & 31;
    if (row >= n_rows) return;

    int b = row / n_per_batch;
    int q = row - b * n_per_batch;
    const float* xb = x + (long long)b * n_per_batch * 3;

    // All 32 lanes read the same 3 addresses -> L1 broadcast.
    float qx = xb[q * 3 + 0];
    float qy = xb[q * 3 + 1];
    float qz = xb[q * 3 + 2];
    float sqq = sq3(qx, qy, qz);

    int i0 = 0, i1 = 0, i2 = 0, i3 = 0, i4 = 0;
    int cnt = 0;

    for (int base = 0; base < n_per_batch; base += 32) {
        int k = base + lane;
        bool valid = (k < n_per_batch);
        int kk = valid ? k : 0;

        float bx = xb[kk * 3 + 0];
        float by = xb[kk * 3 + 1];
        float bz = xb[kk * 3 + 2];
        float sqk = sq3(bx, by, bz);
        float dot = __fmaf_rn(qz, bz, __fmaf_rn(qy, by, __fmul_rn(qx, bx)));
        float d2  = __fsub_rn(__fadd_rn(sqq, sqk), __fmul_rn(2.0f, dot));

        unsigned m = __ballot_sync(0xffffffffu, valid && (d2 < RADIUS2));

        // Extract hits in ascending bit (= ascending k) order; uniform across
        // the warp so no shuffles are needed.
        while (m && cnt < NSAMPLE) {
            int bit = __ffs(m) - 1;
            m &= m - 1;
            int idx = base + bit;
            if (cnt == 0) {
                i0 = idx; i1 = idx; i2 = idx; i3 = idx; i4 = idx;
            } else if (cnt == 1) {
                i1 = idx;
            } else if (cnt == 2) {
                i2 = idx;
            } else if (cnt == 3) {
                i3 = idx;
            } else {
                i4 = idx;
            }
            cnt++;
        }
        if (cnt == NSAMPLE) break;
    }

    if (lane == 0) {
        float* o = out + (long long)row * NSAMPLE;
        o[0] = (float)i0;
        o[1] = (float)i1;
        o[2] = (float)i2;
        o[3] = (float)i3;
        o[4] = (float)i4;
    }
}

extern "C" void kernel_launch(void* const* d_in, const int* in_sizes, int n_in,
                              void* d_out, int out_size) {
    const float* x = (const float*)d_in[0];
    float* out = (float*)d_out;

    int n_rows = out_size / NSAMPLE;       // B * N query rows
    int total_pts = in_sizes[0] / 3;       // B * N points
    int n_per_batch = total_pts / NBATCH;  // N

    int threads = 256;                      // 8 warps -> 8 rows per block
    long long total_threads = (long long)n_rows * 32;
    int blocks = (int)((total_threads + threads - 1) / threads);
    ball_query_warp_kernel<<<blocks, threads>>>(x, out, n_rows, n_per_batch);
}

// round 7
// speedup vs baseline: 1.5481x; 1.2828x over previous
#include <cuda_runtime.h>

// float32(3.4 * 3.4), exactly jnp.float32(RADIUS * RADIUS)
#define RADIUS2 11.559999465942383f
#define NSAMPLE 5
#define NBATCH  8

// sq = (x0*x0 + x1*x1) + x2*x2, each op rounded once — bit-identical to the
// rel_err==0.0 passing version.
__device__ __forceinline__ float sq3(float x0, float x1, float x2) {
    return __fadd_rn(__fadd_rn(__fmul_rn(x0, x0), __fmul_rn(x1, x1)),
                     __fmul_rn(x2, x2));
}

// One warp per query row; 32 candidates per chunk via ballot.
// Fast path: first chunk with >=5 hits -> straight-line extraction of the 5
// lowest set bits (ascending k order == reference scan order).
__global__ void ball_query_warp_kernel(const float* __restrict__ x,  // [B, N, 3]
                                       float* __restrict__ out,      // [B, N, NSAMPLE]
                                       int n_rows, int n_per_batch)
{
    int row  = blockIdx.x * (blockDim.x >> 5) + (threadIdx.x >> 5);
    int lane = threadIdx.x & 31;
    if (row >= n_rows) return;   // whole warp exits together (rows*32 threads)

    int b = row / n_per_batch;
    int q = row - b * n_per_batch;
    const float* xb = x + (long long)b * n_per_batch * 3;

    float qx = xb[q * 3 + 0];
    float qy = xb[q * 3 + 1];
    float qz = xb[q * 3 + 2];
    float sqq = sq3(qx, qy, qz);

    int i0 = 0, i1 = 0, i2 = 0, i3 = 0, i4 = 0;
    int cnt = 0;

    int n_full = n_per_batch & ~31;           // full 32-candidate chunks
    const float* p = xb + lane * 3;           // this lane's candidate pointer

    for (int base = 0; base < n_full; base += 32, p += 96) {
        float bx = p[0];
        float by = p[1];
        float bz = p[2];
        float sqk = sq3(bx, by, bz);
        float dot = __fmaf_rn(qz, bz, __fmaf_rn(qy, by, __fmul_rn(qx, bx)));
        float d2  = __fsub_rn(__fadd_rn(sqq, sqk), __fmul_rn(2.0f, dot));

        unsigned m = __ballot_sync(0xffffffffu, d2 < RADIUS2);
        if (m == 0) continue;

        if (cnt == 0 && __popc(m) >= NSAMPLE) {
            // Fast path (vast majority of rows, chunk 0): extract 5 lowest
            // set bits, straight-line, no loop.
            unsigned t = m;
            i0 = base + __ffs(t) - 1; t &= t - 1;
            i1 = base + __ffs(t) - 1; t &= t - 1;
            i2 = base + __ffs(t) - 1; t &= t - 1;
            i3 = base + __ffs(t) - 1; t &= t - 1;
            i4 = base + __ffs(t) - 1;
            cnt = NSAMPLE;
            break;
        }

        // General path (rare): accumulate hits with first-hit backfill.
        while (m && cnt < NSAMPLE) {
            int idx = base + __ffs(m) - 1;
            m &= m - 1;
            if (cnt == 0) {
                i0 = idx; i1 = idx; i2 = idx; i3 = idx; i4 = idx;
            } else if (cnt == 1) {
                i1 = idx;
            } else if (cnt == 2) {
                i2 = idx;
            } else if (cnt == 3) {
                i3 = idx;
            } else {
                i4 = idx;
            }
            cnt++;
        }
        if (cnt == NSAMPLE) break;
    }

    // Tail chunk (n_per_batch % 32 != 0); skipped entirely for N=4096.
    if (cnt < NSAMPLE && n_full < n_per_batch) {
        int k = n_full + lane;
        bool pred = false;
        if (k < n_per_batch) {
            float bx = xb[k * 3 + 0];
            float by = xb[k * 3 + 1];
            float bz = xb[k * 3 + 2];
            float sqk = sq3(bx, by, bz);
            float dot = __fmaf_rn(qz, bz, __fmaf_rn(qy, by, __fmul_rn(qx, bx)));
            float d2  = __fsub_rn(__fadd_rn(sqq, sqk), __fmul_rn(2.0f, dot));
            pred = (d2 < RADIUS2);
        }
        unsigned m = __ballot_sync(0xffffffffu, pred);
        while (m && cnt < NSAMPLE) {
            int idx = n_full + __ffs(m) - 1;
            m &= m - 1;
            if (cnt == 0) {
                i0 = idx; i1 = idx; i2 = idx; i3 = idx; i4 = idx;
            } else if (cnt == 1) {
                i1 = idx;
            } else if (cnt == 2) {
                i2 = idx;
            } else if (cnt == 3) {
                i3 = idx;
            } else {
                i4 = idx;
            }
            cnt++;
        }
    }

    if (lane == 0) {
        float* o = out + (long long)row * NSAMPLE;
        o[0] = (float)i0;
        o[1] = (float)i1;
        o[2] = (float)i2;
        o[3] = (float)i3;
        o[4] = (float)i4;
    }
}

extern "C" void kernel_launch(void* const* d_in, const int* in_sizes, int n_in,
                              void* d_out, int out_size) {
    const float* x = (const float*)d_in[0];
    float* out = (float*)d_out;

    int n_rows = out_size / NSAMPLE;       // B * N query rows
    int total_pts = in_sizes[0] / 3;       // B * N points
    int n_per_batch = total_pts / NBATCH;  // N

    int threads = 256;                      // 8 warps -> 8 rows per block
    long long total_threads = (long long)n_rows * 32;
    int blocks = (int)((total_threads + threads - 1) / threads);
    ball_query_warp_kernel<<<blocks, threads>>>(x, out, n_rows, n_per_batch);
}

// round 8
// speedup vs baseline: 1.5851x; 1.0239x over previous
#include <cuda_runtime.h>

// float32(3.4 * 3.4), exactly jnp.float32(RADIUS * RADIUS)
#define RADIUS2 11.559999465942383f
#define NSAMPLE 5
#define NBATCH  8
#define STAGE   64          // candidates staged in shared per block

// sq = (x0*x0 + x1*x1) + x2*x2, each op rounded once — bit-identical to the
// rel_err==0.0 passing versions.
__device__ __forceinline__ float sq3(float x0, float x1, float x2) {
    return __fadd_rn(__fadd_rn(__fmul_rn(x0, x0), __fmul_rn(x1, x1)),
                     __fmul_rn(x2, x2));
}

__device__ __forceinline__ float dist2(float qx, float qy, float qz, float sqq,
                                       float bx, float by, float bz, float sqk) {
    float dot = __fmaf_rn(qz, bz, __fmaf_rn(qy, by, __fmul_rn(qx, bx)));
    return __fsub_rn(__fadd_rn(sqq, sqk), __fmul_rn(2.0f, dot));
}

// One THREAD per query row. The first STAGE candidates of the block's batch
// are staged in shared (same points for every row of the batch); each thread
// evaluates them branch-free into a 64-bit hit mask, then extracts the first
// NSAMPLE set bits (ascending bit == ascending k == reference scan order).
// Rare rows with <NSAMPLE hits in the staged range continue with a scalar
// scan from global (L1-resident, broadcast across laggard lanes).
__global__ void ball_query_tpr_kernel(const float* __restrict__ x,  // [B, N, 3]
                                      float* __restrict__ out,      // [B, N, NSAMPLE]
                                      int n_rows, int npb)
{
    __shared__ float4 s_pts[STAGE];

    int row0 = blockIdx.x * blockDim.x;
    int row  = row0 + threadIdx.x;

    // Block-uniform: do all rows of this block belong to one batch, and is
    // the staged range valid?
    int last_row = min(row0 + (int)blockDim.x - 1, n_rows - 1);
    int b0 = row0 / npb;
    bool uniform = (b0 == last_row / npb) && (npb >= STAGE);

    if (uniform && threadIdx.x < STAGE) {
        const float* xb0 = x + (long long)b0 * npb * 3;
        int j = threadIdx.x;
        float bx = xb0[j * 3 + 0];
        float by = xb0[j * 3 + 1];
        float bz = xb0[j * 3 + 2];
        s_pts[j] = make_float4(bx, by, bz, sq3(bx, by, bz));
    }
    __syncthreads();

    if (row >= n_rows) return;

    int b = row / npb;
    int q = row - b * npb;
    const float* xb = x + (long long)b * npb * 3;

    float qx = xb[q * 3 + 0];
    float qy = xb[q * 3 + 1];
    float qz = xb[q * 3 + 2];
    float sqq = sq3(qx, qy, qz);

    unsigned m0 = 0u, m1 = 0u;
    int scanned = 0;
    if (uniform) {
        #pragma unroll
        for (int j = 0; j < 32; j++) {
            float4 p = s_pts[j];
            float d2 = dist2(qx, qy, qz, sqq, p.x, p.y, p.z, p.w);
            m0 |= (d2 < RADIUS2) ? (1u << j) : 0u;
        }
        #pragma unroll
        for (int j = 0; j < 32; j++) {
            float4 p = s_pts[32 + j];
            float d2 = dist2(qx, qy, qz, sqq, p.x, p.y, p.z, p.w);
            m1 |= (d2 < RADIUS2) ? (1u << j) : 0u;
        }
        scanned = STAGE;
    }

    unsigned long long mask = (unsigned long long)m0 |
                              ((unsigned long long)m1 << 32);

    int i0 = 0, i1 = 0, i2 = 0, i3 = 0, i4 = 0;
    int cnt = 0;

    if (__popcll(mask) >= NSAMPLE) {
        // Common path: straight-line extraction of the 5 lowest set bits.
        unsigned long long t = mask;
        i0 = __ffsll(t) - 1; t &= t - 1;
        i1 = __ffsll(t) - 1; t &= t - 1;
        i2 = __ffsll(t) - 1; t &= t - 1;
        i3 = __ffsll(t) - 1; t &= t - 1;
        i4 = __ffsll(t) - 1;
    } else {
        // Rare path: collect partial hits (with first-hit backfill), then
        // continue scanning from global memory.
        unsigned long long t = mask;
        while (t) {
            int idx = __ffsll(t) - 1;
            t &= t - 1;
            if (cnt == 0) {
                i0 = idx; i1 = idx; i2 = idx; i3 = idx; i4 = idx;
            } else if (cnt == 1) {
                i1 = idx;
            } else if (cnt == 2) {
                i2 = idx;
            } else if (cnt == 3) {
                i3 = idx;
            } else {
                i4 = idx;
            }
            cnt++;
        }
        for (int k = scanned; k < npb && cnt < NSAMPLE; k++) {
            float bx = xb[k * 3 + 0];
            float by = xb[k * 3 + 1];
            float bz = xb[k * 3 + 2];
            float d2 = dist2(qx, qy, qz, sqq, bx, by, bz, sq3(bx, by, bz));
            if (d2 < RADIUS2) {
                if (cnt == 0) {
                    i0 = k; i1 = k; i2 = k; i3 = k; i4 = k;
                } else if (cnt == 1) {
                    i1 = k;
                } else if (cnt == 2) {
                    i2 = k;
                } else if (cnt == 3) {
                    i3 = k;
                } else {
                    i4 = k;
                }
                cnt++;
            }
        }
    }

    float* o = out + (long long)row * NSAMPLE;
    o[0] = (float)i0;
    o[1] = (float)i1;
    o[2] = (float)i2;
    o[3] = (float)i3;
    o[4] = (float)i4;
}

extern "C" void kernel_launch(void* const* d_in, const int* in_sizes, int n_in,
                              void* d_out, int out_size) {
    const float* x = (const float*)d_in[0];
    float* out = (float*)d_out;

    int n_rows = out_size / NSAMPLE;       // B * N query rows
    int total_pts = in_sizes[0] / 3;       // B * N points
    int npb = total_pts / NBATCH;          // N per batch

    int threads = 256;                     // 1 thread per row
    int blocks = (n_rows + threads - 1) / threads;
    ball_query_tpr_kernel<<<blocks, threads>>>(x, out, n_rows, npb);
}